// round 5
// baseline (speedup 1.0000x reference)
#include <cuda_runtime.h>
#include <cuda_bf16.h>
#include <cstdint>
#include <math.h>

// ---------------- problem constants ----------------
#define HN     64      // heads
#define PN     64      // head dim
#define GN_    8       // groups
#define NN     128     // state dim
#define CSN    256     // chunk size
#define HIDD   2048
#define INTER  4096    // H*P
#define GNN    1024    // G*N
#define CONVD  6144    // INTER + 2*G*N
#define PROJ   10304   // INTER + CONVD + H
#define LL     2048
#define BB     2
#define TT     4096    // B*L total tokens
#define NCH    16      // total chunks
#define DEADTH (-40.0f)

// ---------------- scratch (__device__ globals; no cudaMalloc allowed) ----------------
__device__ float g_zx   [(size_t)TT * PROJ];                 // in_proj output
__device__ float g_xbc  [(size_t)TT * CONVD];                // conv+silu output
__device__ float g_dt   [(size_t)HN * TT];                   // softplus dt, [h][t]
__device__ float g_dacs [(size_t)HN * TT];                   // per-chunk cumsum dt*A, [h][t]
__device__ float g_cb   [(size_t)NCH * GN_ * CSN * CSN];     // C.B^T per (chunk,group)
__device__ float g_state[(size_t)NCH * HN * PN * NN];
__device__ float g_prev [(size_t)NCH * HN * PN * NN];
__device__ float g_y    [(size_t)TT * INTER];

// ---------------- helpers ----------------
__device__ __forceinline__ uint32_t f2tf(float x) {
    uint32_t r; asm("cvt.rna.tf32.f32 %0, %1;" : "=r"(r) : "f"(x)); return r;
}
__device__ __forceinline__ void mma_tf32(float* c, const uint32_t* a, const uint32_t* b) {
    asm volatile(
        "mma.sync.aligned.m16n8k8.row.col.f32.tf32.tf32.f32 "
        "{%0,%1,%2,%3},{%4,%5,%6,%7},{%8,%9},{%0,%1,%2,%3};\n"
        : "+f"(c[0]), "+f"(c[1]), "+f"(c[2]), "+f"(c[3])
        : "r"(a[0]), "r"(a[1]), "r"(a[2]), "r"(a[3]), "r"(b[0]), "r"(b[1]));
}
__device__ __forceinline__ void cpasync16(uint32_t sdst, const float* gsrc, int srcsz) {
    asm volatile("cp.async.cg.shared.global [%0], [%1], 16, %2;\n"
                 :: "r"(sdst), "l"(gsrc), "r"(srcsz));
}
__device__ __forceinline__ void cpcommit() { asm volatile("cp.async.commit_group;\n"); }
__device__ __forceinline__ void cpwait0()  { asm volatile("cp.async.wait_group 0;\n"); }

__device__ __forceinline__ float siluf(float v) { return v / (1.0f + __expf(-v)); }
__device__ __forceinline__ float softplusf(float x) {
    return (x > 20.0f) ? x : log1pf(__expf(x));
}

// ============================================================
// tf32 GEMM:  C[M,N] = A[M,K] * B[N,K]^T  (row-major, k-contiguous)
// BM=128 BN=128 BK=32, 256 threads, cp.async double buffer.
// Requires M%128==0, K%32==0. N edge guarded.
// ============================================================
#define GBM 128
#define GBK 32
#define GPIT 36
__global__ __launch_bounds__(256) void k_gemm(
    const float* __restrict__ A, const float* __restrict__ B, float* __restrict__ C,
    int M, int N, int K, int lda, int ldb, int ldc)
{
    extern __shared__ float sm[];
    float* sA = sm;                    // [2][128][GPIT]
    float* sB = sm + 2 * 128 * GPIT;   // [2][128][GPIT]

    const int tid  = threadIdx.x;
    const int lane = tid & 31;
    const int warp = tid >> 5;
    const int wm   = warp >> 2;   // 0..1
    const int wn   = warp & 3;    // 0..3
    const int bm0  = blockIdx.y * GBM;
    const int bn0  = blockIdx.x * GBM;

    float acc[4][4][4];
#pragma unroll
    for (int i = 0; i < 4; i++)
#pragma unroll
        for (int j = 0; j < 4; j++)
#pragma unroll
            for (int k = 0; k < 4; k++) acc[i][j][k] = 0.0f;

    const int nk = K / GBK;

    // stage loader
    auto stage = [&](int buf, int k0) {
        float* sa = sA + buf * 128 * GPIT;
        float* sb = sB + buf * 128 * GPIT;
#pragma unroll
        for (int i = 0; i < 4; i++) {
            int f  = tid + i * 256;
            int r  = f >> 3;
            int kv = (f & 7) * 4;
            // A (rows always valid)
            const float* ga = A + (size_t)(bm0 + r) * lda + k0 + kv;
            uint32_t saddr = (uint32_t)__cvta_generic_to_shared(&sa[r * GPIT + kv]);
            cpasync16(saddr, ga, 16);
            // B with n guard
            int br = bn0 + r;
            int brc = br < (N - 1) ? br : (N - 1);
            const float* gb = B + (size_t)brc * ldb + k0 + kv;
            uint32_t sbddr = (uint32_t)__cvta_generic_to_shared(&sb[r * GPIT + kv]);
            cpasync16(sbddr, gb, (br < N) ? 16 : 0);
        }
        cpcommit();
    };

    stage(0, 0);

    for (int kt = 0; kt < nk; kt++) {
        cpwait0();
        __syncthreads();
        if (kt + 1 < nk) stage((kt + 1) & 1, (kt + 1) * GBK);

        const float* a_ = sA + (kt & 1) * 128 * GPIT;
        const float* b_ = sB + (kt & 1) * 128 * GPIT;
        const int ar = wm * 64 + (lane >> 2);
        const int bc = wn * 32 + (lane >> 2);
        const int kc = lane & 3;

#pragma unroll
        for (int kk = 0; kk < 4; kk++) {
            const int k = kk * 8 + kc;
            uint32_t af[4][4], bf[4][2];
#pragma unroll
            for (int mi = 0; mi < 4; mi++) {
                int r0 = ar + mi * 16;
                af[mi][0] = f2tf(a_[r0 * GPIT + k]);
                af[mi][1] = f2tf(a_[(r0 + 8) * GPIT + k]);
                af[mi][2] = f2tf(a_[r0 * GPIT + k + 4]);
                af[mi][3] = f2tf(a_[(r0 + 8) * GPIT + k + 4]);
            }
#pragma unroll
            for (int ni = 0; ni < 4; ni++) {
                int n0 = bc + ni * 8;
                bf[ni][0] = f2tf(b_[n0 * GPIT + k]);
                bf[ni][1] = f2tf(b_[n0 * GPIT + k + 4]);
            }
#pragma unroll
            for (int mi = 0; mi < 4; mi++)
#pragma unroll
                for (int ni = 0; ni < 4; ni++)
                    mma_tf32(acc[mi][ni], af[mi], bf[ni]);
        }
        __syncthreads();
    }

    // epilogue
#pragma unroll
    for (int mi = 0; mi < 4; mi++) {
#pragma unroll
        for (int ni = 0; ni < 4; ni++) {
            int row = bm0 + wm * 64 + mi * 16 + (lane >> 2);
            int col = bn0 + wn * 32 + ni * 8 + (lane & 3) * 2;
            if (col < N) {
                float2 v0 = make_float2(acc[mi][ni][0], acc[mi][ni][1]);
                float2 v1 = make_float2(acc[mi][ni][2], acc[mi][ni][3]);
                *(float2*)&C[(size_t)row * ldc + col]       = v0;
                *(float2*)&C[(size_t)(row + 8) * ldc + col] = v1;
            }
        }
    }
}

// ============================================================
// conv1d (depthwise, causal K=4) + silu over xBC channels
// grid (CONVD/256, TT), 256 thr
// ============================================================
__global__ __launch_bounds__(256) void k_conv(
    const float* __restrict__ conv_w, const float* __restrict__ conv_b)
{
    int c = blockIdx.x * 256 + threadIdx.x;
    int t = blockIdx.y;
    int lt = t & (LL - 1);     // local time within batch
    float w0 = conv_w[c * 4 + 0], w1 = conv_w[c * 4 + 1];
    float w2 = conv_w[c * 4 + 2], w3 = conv_w[c * 4 + 3];
    const float* zp = g_zx + (size_t)t * PROJ + INTER + c;
    float v = conv_b[c];
    if (lt >= 3) v += w0 * zp[-3 * (ptrdiff_t)PROJ];
    if (lt >= 2) v += w1 * zp[-2 * (ptrdiff_t)PROJ];
    if (lt >= 1) v += w2 * zp[-1 * (ptrdiff_t)PROJ];
    v += w3 * zp[0];
    g_xbc[(size_t)t * CONVD + c] = siluf(v);
}

// ============================================================
// dt softplus + per-chunk cumsum of dt*A. grid(16,8), 256 thr (8 warps)
// ============================================================
__global__ __launch_bounds__(256) void k_dtscan(
    const float* __restrict__ A_log, const float* __restrict__ dt_bias)
{
    int warp = threadIdx.x >> 5, lane = threadIdx.x & 31;
    int h = blockIdx.y * 8 + warp;
    int chunk = blockIdx.x;
    float Ah = -__expf(A_log[h]);
    float bias = dt_bias[h];
    int tbase = chunk * CSN + lane * 8;

    float pre[8];
    float run = 0.0f;
    float dts[8];
#pragma unroll
    for (int k = 0; k < 8; k++) {
        float raw = g_zx[(size_t)(tbase + k) * PROJ + (INTER + CONVD) + h];
        float dt = softplusf(raw + bias);
        dts[k] = dt;
        run += dt * Ah;
        pre[k] = run;
    }
    float tot = run;
#pragma unroll
    for (int off = 1; off < 32; off <<= 1) {
        float n = __shfl_up_sync(0xffffffffu, tot, off);
        if (lane >= off) tot += n;
    }
    float excl = tot - run;  // exclusive prefix across lanes
#pragma unroll
    for (int k = 0; k < 8; k++) {
        g_dt  [(size_t)h * TT + tbase + k] = dts[k];
        g_dacs[(size_t)h * TT + tbase + k] = pre[k] + excl;
    }
}

// ============================================================
// CB[cg][i][j] = sum_n C[i,n]*B[j,n]   (lower-triangular 64x64 tiles)
// grid (16 tiles, 128 cg), 256 thr
// NOTE: smem pitch 33 is NOT 16B-aligned per row -> scalar STS only.
// ============================================================
__global__ __launch_bounds__(256) void k_cb()
{
    int tile = blockIdx.x;
    int ti = tile >> 2, tj = tile & 3;
    if (ti < tj) return;
    int cg = blockIdx.y;
    int chunk = cg >> 3, g = cg & 7;

    __shared__ float sC[64][33];
    __shared__ float sB[64][33];

    int tid = threadIdx.x;
    int ty = tid >> 4, tx = tid & 15;
    float acc[4][4];
#pragma unroll
    for (int r = 0; r < 4; r++)
#pragma unroll
        for (int c = 0; c < 4; c++) acc[r][c] = 0.0f;

    const size_t cBase = (size_t)(chunk * CSN) * CONVD + INTER + GNN + (size_t)g * NN;
    const size_t bBase = (size_t)(chunk * CSN) * CONVD + INTER + (size_t)g * NN;

    for (int kt = 0; kt < 4; kt++) {
        int k0 = kt * 32;
#pragma unroll
        for (int i = 0; i < 2; i++) {
            int f = tid + i * 256;       // 0..511 float4s
            int r = f >> 3, kv = (f & 7) * 4;
            float4 cv = *(const float4*)&g_xbc[cBase + (size_t)(ti * 64 + r) * CONVD + k0 + kv];
            float4 bv = *(const float4*)&g_xbc[bBase + (size_t)(tj * 64 + r) * CONVD + k0 + kv];
            sC[r][kv + 0] = cv.x; sC[r][kv + 1] = cv.y;
            sC[r][kv + 2] = cv.z; sC[r][kv + 3] = cv.w;
            sB[r][kv + 0] = bv.x; sB[r][kv + 1] = bv.y;
            sB[r][kv + 2] = bv.z; sB[r][kv + 3] = bv.w;
        }
        __syncthreads();
#pragma unroll
        for (int kk = 0; kk < 32; kk++) {
            float a[4], b[4];
#pragma unroll
            for (int r = 0; r < 4; r++) a[r] = sC[ty * 4 + r][kk];
#pragma unroll
            for (int c = 0; c < 4; c++) b[c] = sB[tx * 4 + c][kk];
#pragma unroll
            for (int r = 0; r < 4; r++)
#pragma unroll
                for (int c = 0; c < 4; c++) acc[r][c] += a[r] * b[c];
        }
        __syncthreads();
    }
    float* out = g_cb + (size_t)cg * (CSN * CSN);
#pragma unroll
    for (int r = 0; r < 4; r++) {
        int i = ti * 64 + ty * 4 + r;
        int j = tj * 64 + tx * 4;
        *(float4*)&out[(size_t)i * CSN + j] = make_float4(acc[r][0], acc[r][1], acc[r][2], acc[r][3]);
    }
}

// ============================================================
// Y_diag + D*x  -> g_y.   grid (4 i-tiles, 16 chunks, 64 heads), 256 thr
// Masked attention with decay pruning (tiles with exp < e^-40 skipped)
// ============================================================
__global__ __launch_bounds__(256) void k_ydiag(const float* __restrict__ Dv)
{
    int it = blockIdx.x;       // i-tile of 64
    int chunk = blockIdx.y;
    int h = blockIdx.z;
    int g = h >> 3;
    int i0 = it * 64;
    int tid = threadIdx.x;
    int ty = tid >> 4, tx = tid & 15;
    int p0 = tx * 4;

    __shared__ __align__(16) float sx[32][68];   // pitch 68*4=272B = 17*16 -> float4 ok
    __shared__ float sM[32][65];
    __shared__ float sdj[32], sdtj[32], sdi[64];

    const float* dac = g_dacs + (size_t)h * TT + chunk * CSN;
    const float* dtp = g_dt   + (size_t)h * TT + chunk * CSN;
    const float* cbp = g_cb + (size_t)(chunk * 8 + g) * (CSN * CSN);

    if (tid < 64) sdi[tid] = dac[i0 + tid];
    __syncthreads();

    float acc[4][4];
#pragma unroll
    for (int r = 0; r < 4; r++)
#pragma unroll
        for (int c = 0; c < 4; c++) acc[r][c] = 0.0f;

    float dc_i0 = dac[i0];

    for (int jt = 2 * it + 1; jt >= 0; jt--) {
        int j0 = jt * 32;
        bool overlap = (j0 + 32 > i0);
        if (!overlap) {
            float d = dc_i0 - dac[j0 + 31];
            if (d < DEADTH) break;    // monotone: all earlier tiles dead too
        }
        // load dt/dacs for j range + x tile
        if (tid < 32) { sdj[tid] = dac[j0 + tid]; sdtj[tid] = dtp[j0 + tid]; }
        __syncthreads();
#pragma unroll
        for (int i = 0; i < 2; i++) {
            int f = tid + i * 256;    // 512 float4s = 32x64
            int j = f >> 4, pv = (f & 15) * 4;
            *(float4*)&sx[j][pv] =
                *(const float4*)&g_xbc[(size_t)(chunk * CSN + j0 + j) * CONVD + h * PN + pv];
        }
        __syncthreads();
        // phase 1: build M tile (each exp computed exactly once)
        {
            int im = tid >> 2;            // 0..63
            int jb = (tid & 3) * 8;       // 0..24
            float di = sdi[im];
            int gi = i0 + im;
            float4 cb0 = *(const float4*)&cbp[(size_t)gi * CSN + j0 + jb];
            float4 cb1 = *(const float4*)&cbp[(size_t)gi * CSN + j0 + jb + 4];
            float cbv[8] = {cb0.x, cb0.y, cb0.z, cb0.w, cb1.x, cb1.y, cb1.z, cb1.w};
#pragma unroll
            for (int k = 0; k < 8; k++) {
                int j = jb + k;
                int gj = j0 + j;
                float m = 0.0f;
                if (gj <= gi) {
                    float d = fmaxf(di - sdj[j], -80.0f);
                    m = cbv[k] * __expf(d) * sdtj[j];
                }
                sM[j][im] = m;
            }
        }
        __syncthreads();
        // phase 2: acc += M * x
#pragma unroll 4
        for (int j = 0; j < 32; j++) {
            float4 xv = *(const float4*)&sx[j][p0];
#pragma unroll
            for (int r = 0; r < 4; r++) {
                float m = sM[j][ty * 4 + r];
                acc[r][0] += m * xv.x;
                acc[r][1] += m * xv.y;
                acc[r][2] += m * xv.z;
                acc[r][3] += m * xv.w;
            }
        }
        __syncthreads();
    }

    float Dh = Dv[h];
#pragma unroll
    for (int r = 0; r < 4; r++) {
        int i = i0 + ty * 4 + r;
        int t = chunk * CSN + i;
        float4 xv = *(const float4*)&g_xbc[(size_t)t * CONVD + h * PN + p0];
        float4 o = make_float4(acc[r][0] + Dh * xv.x, acc[r][1] + Dh * xv.y,
                               acc[r][2] + Dh * xv.z, acc[r][3] + Dh * xv.w);
        *(float4*)&g_y[(size_t)t * INTER + h * PN + p0] = o;
    }
}

// ============================================================
// states[c,h,p,n] = sum_j w_j * x[j,p] * B[j,n], pruned from the end.
// grid (16, 64), 256 thr
// ============================================================
__global__ __launch_bounds__(256) void k_states()
{
    int chunk = blockIdx.x, h = blockIdx.y, g = h >> 3;
    int tid = threadIdx.x;
    int ty = tid >> 4, tx = tid & 15;
    int p0 = ty * 4, n0 = tx * 8;

    __shared__ __align__(16) float sxw[32][68];   // 272B pitch
    __shared__ __align__(16) float sB[32][132];   // 528B pitch = 33*16
    __shared__ float sw[32];

    const float* dac = g_dacs + (size_t)h * TT + chunk * CSN;
    const float* dtp = g_dt   + (size_t)h * TT + chunk * CSN;
    float dlast = dac[CSN - 1];

    float acc[4][8];
#pragma unroll
    for (int r = 0; r < 4; r++)
#pragma unroll
        for (int c = 0; c < 8; c++) acc[r][c] = 0.0f;

    for (int jt = 7; jt >= 0; jt--) {
        int j0 = jt * 32;
        if (dlast - dac[j0 + 31] < DEADTH) break;
        if (tid < 32)
            sw[tid] = __expf(fmaxf(dlast - dac[j0 + tid], -80.0f)) * dtp[j0 + tid];
        __syncthreads();
#pragma unroll
        for (int i = 0; i < 2; i++) {
            int f = tid + i * 256;
            int j = f >> 4, pv = (f & 15) * 4;
            float4 xv = *(const float4*)&g_xbc[(size_t)(chunk * CSN + j0 + j) * CONVD + h * PN + pv];
            float w = sw[j];
            xv.x *= w; xv.y *= w; xv.z *= w; xv.w *= w;
            *(float4*)&sxw[j][pv] = xv;
        }
#pragma unroll
        for (int i = 0; i < 4; i++) {
            int f = tid + i * 256;     // 1024 float4s = 32x128
            int j = f >> 5, nv = (f & 31) * 4;
            *(float4*)&sB[j][nv] =
                *(const float4*)&g_xbc[(size_t)(chunk * CSN + j0 + j) * CONVD + INTER + g * NN + nv];
        }
        __syncthreads();
#pragma unroll 2
        for (int j = 0; j < 32; j++) {
            float4 xv = *(const float4*)&sxw[j][p0];
            float4 b0 = *(const float4*)&sB[j][n0];
            float4 b1 = *(const float4*)&sB[j][n0 + 4];
            float xr[4] = {xv.x, xv.y, xv.z, xv.w};
            float bb[8] = {b0.x, b0.y, b0.z, b0.w, b1.x, b1.y, b1.z, b1.w};
#pragma unroll
            for (int r = 0; r < 4; r++)
#pragma unroll
                for (int c = 0; c < 8; c++) acc[r][c] += xr[r] * bb[c];
        }
        __syncthreads();
    }

    float* out = g_state + (size_t)(chunk * HN + h) * (PN * NN);
#pragma unroll
    for (int r = 0; r < 4; r++) {
        *(float4*)&out[(size_t)(p0 + r) * NN + n0]     = make_float4(acc[r][0], acc[r][1], acc[r][2], acc[r][3]);
        *(float4*)&out[(size_t)(p0 + r) * NN + n0 + 4] = make_float4(acc[r][4], acc[r][5], acc[r][6], acc[r][7]);
    }
}

// ============================================================
// inter-chunk scan: prev[c] = S before chunk c. grid (2, 64), 256 thr
// ============================================================
__global__ __launch_bounds__(256) void k_scan()
{
    int b = blockIdx.x, h = blockIdx.y;
    int tid = threadIdx.x;
    float acc[32];
#pragma unroll
    for (int k = 0; k < 32; k++) acc[k] = 0.0f;
    for (int cl = 0; cl < 8; cl++) {
        int chunk = b * 8 + cl;
        size_t base = (size_t)(chunk * HN + h) * (PN * NN);
#pragma unroll
        for (int k = 0; k < 32; k++) g_prev[base + tid + k * 256] = acc[k];
        float decay = __expf(fmaxf(g_dacs[(size_t)h * TT + chunk * CSN + CSN - 1], -80.0f));
#pragma unroll
        for (int k = 0; k < 32; k++)
            acc[k] = decay * acc[k] + g_state[base + tid + k * 256];
    }
}

// ============================================================
// Y_off: g_y += exp(dacs_i) * C_i . prev[h]^T   (row-pruned)
// grid (16, 64), 256 thr
// ============================================================
__global__ __launch_bounds__(256) void k_yoff()
{
    int chunk = blockIdx.x;
    if ((chunk & 7) == 0) return;   // first chunk of batch: prev == 0
    int h = blockIdx.y, g = h >> 3;
    const float* dac = g_dacs + (size_t)h * TT + chunk * CSN;
    if (dac[0] < DEADTH) return;    // whole chunk dead for this head

    __shared__ __align__(16) float sPT[128][64];  // prev transposed [n][p], 256B pitch
    __shared__ __align__(16) float sC[16][128];   // 512B pitch

    int tid = threadIdx.x;
    size_t pbase = (size_t)(chunk * HN + h) * (PN * NN);
#pragma unroll
    for (int k = 0; k < 32; k++) {
        int idx = tid + k * 256;
        int p = idx >> 7, n = idx & 127;
        sPT[n][p] = g_prev[pbase + idx];
    }
    __syncthreads();

    int im = tid >> 4;          // 0..15
    int p0 = (tid & 15) * 4;

    for (int it = 0; it < 16; it++) {
        int i0 = it * 16;
        if (dac[i0] < DEADTH) break;
        // load C tile 16x128
#pragma unroll
        for (int k = 0; k < 2; k++) {
            int f = tid + k * 256;    // 512 float4s = 16x128
            int i = f >> 5, nv = (f & 31) * 4;
            *(float4*)&sC[i][nv] =
                *(const float4*)&g_xbc[(size_t)(chunk * CSN + i0 + i) * CONVD + INTER + GNN + g * NN + nv];
        }
        __syncthreads();
        float4 acc = make_float4(0.f, 0.f, 0.f, 0.f);
#pragma unroll 4
        for (int n = 0; n < 128; n++) {
            float cv = sC[im][n];
            float4 pv = *(const float4*)&sPT[n][p0];
            acc.x += cv * pv.x; acc.y += cv * pv.y;
            acc.z += cv * pv.z; acc.w += cv * pv.w;
        }
        float e = __expf(fmaxf(dac[i0 + im], -80.0f));
        int t = chunk * CSN + i0 + im;
        float4 o = *(float4*)&g_y[(size_t)t * INTER + h * PN + p0];
        o.x += e * acc.x; o.y += e * acc.y; o.z += e * acc.z; o.w += e * acc.w;
        *(float4*)&g_y[(size_t)t * INTER + h * PN + p0] = o;
        __syncthreads();
    }
}

// ============================================================
// RMSNorm * silu(z) gate, in place on g_y. grid (4096), 256 thr
// ============================================================
__global__ __launch_bounds__(256) void k_norm(const float* __restrict__ norm_w)
{
    int t = blockIdx.x;
    int tid = threadIdx.x;
    __shared__ float red[8];
    float* yp = g_y + (size_t)t * INTER;
    const float* zp = g_zx + (size_t)t * PROJ;

    float ss = 0.0f;
#pragma unroll
    for (int k = 0; k < 16; k++) {
        float v = yp[tid + k * 256];
        ss += v * v;
    }
#pragma unroll
    for (int off = 16; off >= 1; off >>= 1) ss += __shfl_xor_sync(0xffffffffu, ss, off);
    if ((tid & 31) == 0) red[tid >> 5] = ss;
    __syncthreads();
    if (tid == 0) {
        float tot = 0.0f;
#pragma unroll
        for (int i = 0; i < 8; i++) tot += red[i];
        red[0] = rsqrtf(tot * (1.0f / INTER) + 1e-5f);
    }
    __syncthreads();
    float rinv = red[0];
#pragma unroll
    for (int k = 0; k < 16; k++) {
        int c = tid + k * 256;
        float v = yp[c];
        float z = zp[c];
        yp[c] = norm_w[c] * v * rinv * siluf(z);
    }
}

// ============================================================
// launch
// ============================================================
extern "C" void kernel_launch(void* const* d_in, const int* in_sizes, int n_in,
                              void* d_out, int out_size)
{
    const float* hidden   = (const float*)d_in[0];
    const float* in_w     = (const float*)d_in[1];
    const float* conv_w   = (const float*)d_in[2];
    const float* conv_b   = (const float*)d_in[3];
    const float* dt_bias  = (const float*)d_in[4];
    const float* A_log    = (const float*)d_in[5];
    const float* Dv       = (const float*)d_in[6];
    const float* norm_w   = (const float*)d_in[7];
    const float* out_w    = (const float*)d_in[8];
    float* outp = (float*)d_out;

    float* zx; cudaGetSymbolAddress((void**)&zx, g_zx);
    float* yy; cudaGetSymbolAddress((void**)&yy, g_y);

    static int smem_set = 0;
    const int gemm_smem = 2 * 2 * 128 * GPIT * (int)sizeof(float); // 73728
    if (!smem_set) {
        cudaFuncSetAttribute(k_gemm, cudaFuncAttributeMaxDynamicSharedMemorySize, gemm_smem);
        smem_set = 1;
    }

    // 1. in_proj:  zx[T, PROJ] = hidden[T, HIDD] @ in_w[PROJ, HIDD]^T
    {
        dim3 grid((PROJ + 127) / 128, TT / 128);
        k_gemm<<<grid, 256, gemm_smem>>>(hidden, in_w, zx, TT, PROJ, HIDD, HIDD, HIDD, PROJ);
    }
    // 2. conv + silu
    k_conv<<<dim3(CONVD / 256, TT), 256>>>(conv_w, conv_b);
    // 3. dt softplus + cumsum
    k_dtscan<<<dim3(NCH, 8), 256>>>(A_log, dt_bias);
    // 4. CB
    k_cb<<<dim3(16, NCH * GN_), 256>>>();
    // 5. Y_diag + D*x
    k_ydiag<<<dim3(4, NCH, HN), 256>>>(Dv);
    // 6. states
    k_states<<<dim3(NCH, HN), 256>>>();
    // 7. scan
    k_scan<<<dim3(BB, HN), 256>>>();
    // 8. Y_off
    k_yoff<<<dim3(NCH, HN), 256>>>();
    // 9. rmsnorm + gate
    k_norm<<<TT, 256>>>(norm_w);
    // 10. out_proj: out[T, HIDD] = y[T, INTER] @ out_w[HIDD, INTER]^T
    {
        dim3 grid(HIDD / 128, TT / 128);
        k_gemm<<<grid, 256, gemm_smem>>>(yy, out_w, outp, TT, HIDD, INTER, INTER, INTER, HIDD);
    }
    (void)in_sizes; (void)n_in; (void)out_size;
}